// round 9
// baseline (speedup 1.0000x reference)
#include <cuda_runtime.h>
#include <cuda_bf16.h>
#include <cstddef>
#include <cstdint>

#define Bq   128
#define Tq   64
#define Hq   512
#define Vq   10000
#define Gq   2048            // 4*H
#define BTq  (Bq*Tq)         // 8192
#define NBLK 79              // ceil(V/128)

// ---------------- scratch ----------------
__device__ float g_xw0[(size_t)BTq * Gq];
__device__ float g_out[(size_t)BTq * Hq];
__device__ float g_pm[(size_t)BTq * NBLK];
__device__ float g_ps[(size_t)BTq * NBLK];
__device__ float g_zl[BTq];
__device__ float g_xent[BTq];
__device__ float g_h0[2][Bq * Hq];
__device__ float g_h1[2][Bq * Hq];
__device__ float g_c0[Bq * Hq];
__device__ float g_c1[Bq * Hq];
__device__ float g_o0[Bq * Hq];

__device__ __forceinline__ float sigf(float x) { return 1.f / (1.f + expf(-x)); }

__device__ __forceinline__ uint32_t s2u(const void* p) {
    return (uint32_t)__cvta_generic_to_shared(p);
}
__device__ __forceinline__ void cpa16(uint32_t dst, const void* src) {
    asm volatile("cp.async.cg.shared.global [%0], [%1], 16;" :: "r"(dst), "l"(src));
}
__device__ __forceinline__ void cpa16p(uint32_t dst, const void* src, bool pred) {
    int sz = pred ? 16 : 0;
    asm volatile("cp.async.cg.shared.global [%0], [%1], 16, %2;" :: "r"(dst), "l"(src), "r"(sz));
}
#define CP_COMMIT asm volatile("cp.async.commit_group;")
#define CP_WAIT1  asm volatile("cp.async.wait_group 1;")

__device__ __forceinline__ void mma_tf32(float& d0, float& d1, float& d2, float& d3,
                                         unsigned a0, unsigned a1, unsigned a2, unsigned a3,
                                         unsigned b0, unsigned b1) {
    asm volatile(
        "mma.sync.aligned.m16n8k8.row.col.f32.tf32.tf32.f32 "
        "{%0,%1,%2,%3}, {%4,%5,%6,%7}, {%8,%9}, {%0,%1,%2,%3};"
        : "+f"(d0), "+f"(d1), "+f"(d2), "+f"(d3)
        : "r"(a0), "r"(a1), "r"(a2), "r"(a3), "r"(b0), "r"(b1));
}

// ---------------- init ----------------
__global__ void k_init() {
    int i = blockIdx.x * blockDim.x + threadIdx.x;
    if (i < Bq * Hq) {
        g_h0[0][i] = 0.f; g_c0[i] = 0.f;
        g_h1[0][i] = 0.f; g_c1[i] = 0.f;
    }
}

// =======================================================================
// big tf32 GEMMs: block 128x128, warp 32x64, k-chunk 16, 2-stage cp.async
// =======================================================================
#define ASTR 20
#define BSTR 136

__global__ void k_xw0_tf32(const float* __restrict__ emb, const int* __restrict__ feat,
                           const float* __restrict__ Bm, const float* __restrict__ bias) {
    const int N = Gq, K = Hq;
    __shared__ float As[2][128 * ASTR];
    __shared__ float Bs[2][16 * BSTR];
    const int tid = threadIdx.x;
    const int bx = blockIdx.x, by = blockIdx.y;
    const int warp = tid >> 5, lane = tid & 31;
    const int wm = warp & 3, wn = warp >> 2;
    const int gID = lane >> 2, tig = lane & 3;

    const int arow = tid >> 2;
    const int aq   = (tid & 3) * 4;
    const float* asrc0 = emb + (size_t)feat[by * 128 + arow] * K + aq;
    const float* asrc1 = emb + (size_t)feat[by * 128 + arow + 64] * K + aq;
    const int bk = tid >> 5, bq = tid & 31;
    const float* bsrc = Bm + (size_t)bk * N + bx * 128 + bq * 4;

    float acc[2][8][4];
#pragma unroll
    for (int mt = 0; mt < 2; ++mt)
#pragma unroll
        for (int nt = 0; nt < 8; ++nt)
#pragma unroll
            for (int e = 0; e < 4; ++e) acc[mt][nt][e] = 0.f;

    const int NC = K / 16;
    {
        cpa16(s2u(&As[0][arow * ASTR + aq]), asrc0);
        cpa16(s2u(&As[0][(arow + 64) * ASTR + aq]), asrc1);
        cpa16(s2u(&Bs[0][bk * BSTR + bq * 4]), bsrc);
        cpa16(s2u(&Bs[0][(bk + 8) * BSTR + bq * 4]), bsrc + (size_t)8 * N);
    }
    CP_COMMIT;
    for (int c = 0; c < NC; ++c) {
        const int cur = c & 1, nxt = cur ^ 1;
        if (c + 1 < NC) {
            int k0 = (c + 1) * 16;
            cpa16(s2u(&As[nxt][arow * ASTR + aq]), asrc0 + k0);
            cpa16(s2u(&As[nxt][(arow + 64) * ASTR + aq]), asrc1 + k0);
            cpa16(s2u(&Bs[nxt][bk * BSTR + bq * 4]), bsrc + (size_t)k0 * N);
            cpa16(s2u(&Bs[nxt][(bk + 8) * BSTR + bq * 4]), bsrc + (size_t)(k0 + 8) * N);
        }
        CP_COMMIT;
        CP_WAIT1;
        __syncthreads();
        const unsigned* Au = (const unsigned*)As[cur];
        const unsigned* Bu = (const unsigned*)Bs[cur];
#pragma unroll
        for (int ks = 0; ks < 2; ++ks) {
            unsigned a[2][4];
#pragma unroll
            for (int mt = 0; mt < 2; ++mt) {
                int mr = wm * 32 + mt * 16;
                a[mt][0] = Au[(mr + gID    ) * ASTR + ks * 8 + tig];
                a[mt][1] = Au[(mr + gID + 8) * ASTR + ks * 8 + tig];
                a[mt][2] = Au[(mr + gID    ) * ASTR + ks * 8 + tig + 4];
                a[mt][3] = Au[(mr + gID + 8) * ASTR + ks * 8 + tig + 4];
            }
#pragma unroll
            for (int nt = 0; nt < 8; ++nt) {
                int nc = wn * 64 + nt * 8 + gID;
                unsigned b0 = Bu[(ks * 8 + tig    ) * BSTR + nc];
                unsigned b1 = Bu[(ks * 8 + tig + 4) * BSTR + nc];
#pragma unroll
                for (int mt = 0; mt < 2; ++mt)
                    mma_tf32(acc[mt][nt][0], acc[mt][nt][1], acc[mt][nt][2], acc[mt][nt][3],
                             a[mt][0], a[mt][1], a[mt][2], a[mt][3], b0, b1);
            }
        }
        __syncthreads();
    }
#pragma unroll
    for (int mt = 0; mt < 2; ++mt) {
#pragma unroll
        for (int er = 0; er < 2; ++er) {
            int gm = by * 128 + wm * 32 + mt * 16 + gID + er * 8;
            float* crow = g_xw0 + (size_t)gm * N;
#pragma unroll
            for (int nt = 0; nt < 8; ++nt) {
                int gn = bx * 128 + wn * 64 + nt * 8 + tig * 2;
                float2 v = {acc[mt][nt][er * 2 + 0] + bias[gn],
                            acc[mt][nt][er * 2 + 1] + bias[gn + 1]};
                *(float2*)(crow + gn) = v;
            }
        }
    }
}

__global__ void k_logits_tf32(const float* __restrict__ Bm,
                              const float* __restrict__ bias,
                              const int* __restrict__ labels) {
    const int N = Vq, K = Hq;
    __shared__ float As[2][128 * ASTR];
    __shared__ float Bs[2][16 * BSTR];
    __shared__ float pm[128][9];
    __shared__ float ps[128][9];
    const int tid = threadIdx.x;
    const int bx = blockIdx.x, by = blockIdx.y;
    const int warp = tid >> 5, lane = tid & 31;
    const int wm = warp & 3, wn = warp >> 2;
    const int gID = lane >> 2, tig = lane & 3;

    const int arow = tid >> 2;
    const int aq   = (tid & 3) * 4;
    const float* asrc0 = g_out + (size_t)(by * 128 + arow) * K + aq;
    const float* asrc1 = asrc0 + (size_t)64 * K;
    const int bk = tid >> 5, bq = tid & 31;
    const int gnq = bx * 128 + bq * 4;
    const bool bpred = (gnq + 3 < N);
    const float* bsrc = Bm + (size_t)bk * N + (bpred ? gnq : 0);

    float acc[2][8][4];
#pragma unroll
    for (int mt = 0; mt < 2; ++mt)
#pragma unroll
        for (int nt = 0; nt < 8; ++nt)
#pragma unroll
            for (int e = 0; e < 4; ++e) acc[mt][nt][e] = 0.f;

    const int NC = K / 16;
    {
        cpa16(s2u(&As[0][arow * ASTR + aq]), asrc0);
        cpa16(s2u(&As[0][(arow + 64) * ASTR + aq]), asrc1);
        cpa16p(s2u(&Bs[0][bk * BSTR + bq * 4]), bsrc, bpred);
        cpa16p(s2u(&Bs[0][(bk + 8) * BSTR + bq * 4]), bsrc + (size_t)8 * N, bpred);
    }
    CP_COMMIT;
    for (int c = 0; c < NC; ++c) {
        const int cur = c & 1, nxt = cur ^ 1;
        if (c + 1 < NC) {
            int k0 = (c + 1) * 16;
            cpa16(s2u(&As[nxt][arow * ASTR + aq]), asrc0 + k0);
            cpa16(s2u(&As[nxt][(arow + 64) * ASTR + aq]), asrc1 + k0);
            cpa16p(s2u(&Bs[nxt][bk * BSTR + bq * 4]), bsrc + (size_t)k0 * N, bpred);
            cpa16p(s2u(&Bs[nxt][(bk + 8) * BSTR + bq * 4]), bsrc + (size_t)(k0 + 8) * N, bpred);
        }
        CP_COMMIT;
        CP_WAIT1;
        __syncthreads();
        const unsigned* Au = (const unsigned*)As[cur];
        const unsigned* Bu = (const unsigned*)Bs[cur];
#pragma unroll
        for (int ks = 0; ks < 2; ++ks) {
            unsigned a[2][4];
#pragma unroll
            for (int mt = 0; mt < 2; ++mt) {
                int mr = wm * 32 + mt * 16;
                a[mt][0] = Au[(mr + gID    ) * ASTR + ks * 8 + tig];
                a[mt][1] = Au[(mr + gID + 8) * ASTR + ks * 8 + tig];
                a[mt][2] = Au[(mr + gID    ) * ASTR + ks * 8 + tig + 4];
                a[mt][3] = Au[(mr + gID + 8) * ASTR + ks * 8 + tig + 4];
            }
#pragma unroll
            for (int nt = 0; nt < 8; ++nt) {
                int nc = wn * 64 + nt * 8 + gID;
                unsigned b0 = Bu[(ks * 8 + tig    ) * BSTR + nc];
                unsigned b1 = Bu[(ks * 8 + tig + 4) * BSTR + nc];
#pragma unroll
                for (int mt = 0; mt < 2; ++mt)
                    mma_tf32(acc[mt][nt][0], acc[mt][nt][1], acc[mt][nt][2], acc[mt][nt][3],
                             a[mt][0], a[mt][1], a[mt][2], a[mt][3], b0, b1);
            }
        }
        __syncthreads();
    }

#pragma unroll
    for (int mt = 0; mt < 2; ++mt) {
#pragma unroll
        for (int er = 0; er < 2; ++er) {
            int lr = wm * 32 + mt * 16 + gID + er * 8;
            int gm = by * 128 + lr;
            int lab = labels[gm];
            float lm = -1e30f, lsum = 0.f;
            float v[16];
#pragma unroll
            for (int nt = 0; nt < 8; ++nt) {
#pragma unroll
                for (int e = 0; e < 2; ++e) {
                    int gn = bx * 128 + wn * 64 + nt * 8 + tig * 2 + e;
                    float cc = acc[mt][nt][er * 2 + e];
                    if (gn < N) {
                        float z = cc + bias[gn];
                        v[nt * 2 + e] = z;
                        if (gn == lab) g_zl[gm] = z;
                        lm = fmaxf(lm, z);
                    } else v[nt * 2 + e] = -1e30f;
                }
            }
#pragma unroll
            for (int q = 0; q < 16; ++q) lsum += expf(v[q] - lm);
            if (lm <= -1e30f) lsum = 0.f;
            pm[lr][wn * 4 + tig] = lm;
            ps[lr][wn * 4 + tig] = lsum;
        }
    }
    __syncthreads();
    if (tid < 128) {
        float m = -1e30f, s = 0.f;
#pragma unroll
        for (int x = 0; x < 8; ++x) {
            float m2 = pm[tid][x], s2 = ps[tid][x];
            float M = fmaxf(m, m2);
            s = s * expf(m - M) + s2 * expf(m2 - M);
            m = M;
        }
        int gm = by * 128 + tid;
        g_pm[(size_t)gm * NBLK + bx] = m;
        g_ps[(size_t)gm * NBLK + bx] = s;
    }
}

// =======================================================================
// tf32 tensor-core LSTM steps — k-chunk 32, 3-stage cp.async pipeline,
// ONE __syncthreads per iteration (wait -> sync -> issue -> commit -> mma).
// Grid 128 blocks = 128 rows x 16 gate-cols (j0 = bx*4).  Dynamic SMEM:
// 3 stages x (A[128][36] + B[32][24]) = 64.5 KB.
// =======================================================================
#define SA2   36
#define SB2   24
#define STGF  (128 * SA2 + 32 * SB2)            // floats per stage
#define STEP_SMEM (3 * STGF * 4)                // bytes

struct StepPre {
    float ga[2][4];
    float cold[2], hold[2];
    int   sl[2], b_[2], j_[2];
};

__device__ __forceinline__ void step_mma_loop(
        const float* __restrict__ A0, const float* __restrict__ A1,
        const float* __restrict__ W0, const float* __restrict__ W1,
        int nphase, int j0, float* dynsm,
        int tid, int wm, int gID, int tig, float acc[2][4]) {
    const int ar = tid >> 1, ah = (tid & 1) * 16;   // A: row, k-half
    const int bk = tid >> 2, bg = tid & 3;          // B: tid<128
    const int NC = nphase * 16;                     // chunks of 32 over K

    auto issue = [&](int cc) {
        const float* Ap = (cc < 16) ? A0 : A1;
        const float* Wp = (cc < 16) ? W0 : W1;
        int k0 = (cc & 15) * 32;
        float* Ab = dynsm + (cc % 3) * STGF;
        float* Bb = Ab + 128 * SA2;
        const float* as = Ap + (size_t)ar * Hq + k0 + ah;
        uint32_t ad = s2u(&Ab[ar * SA2 + ah]);
        cpa16(ad,      as);
        cpa16(ad + 16, as + 4);
        cpa16(ad + 32, as + 8);
        cpa16(ad + 48, as + 12);
        if (tid < 128)
            cpa16(s2u(&Bb[bk * SB2 + bg * 4]),
                  Wp + (size_t)(k0 + bk) * Gq + bg * Hq + j0);
    };

    issue(0); CP_COMMIT;
    issue(1); CP_COMMIT;
    for (int c = 0; c < NC; ++c) {
        CP_WAIT1;                    // all groups older than the most recent done -> chunk c landed
        __syncthreads();             // everyone finished mma on buf (c-1)%3 == (c+2)%3
        if (c + 2 < NC) issue(c + 2);
        CP_COMMIT;                   // unconditional: keeps index bookkeeping exact
        const unsigned* Au = (const unsigned*)(dynsm + (c % 3) * STGF);
        const unsigned* Bu = Au + 128 * SA2;
#pragma unroll
        for (int ks = 0; ks < 4; ++ks) {
            unsigned a0 = Au[(wm * 16 + gID    ) * SA2 + ks * 8 + tig];
            unsigned a1 = Au[(wm * 16 + gID + 8) * SA2 + ks * 8 + tig];
            unsigned a2 = Au[(wm * 16 + gID    ) * SA2 + ks * 8 + tig + 4];
            unsigned a3 = Au[(wm * 16 + gID + 8) * SA2 + ks * 8 + tig + 4];
#pragma unroll
            for (int nt = 0; nt < 2; ++nt) {
                int n = nt * 8 + gID;
                unsigned b0 = Bu[(ks * 8 + tig    ) * SB2 + n];
                unsigned b1 = Bu[(ks * 8 + tig + 4) * SB2 + n];
                mma_tf32(acc[nt][0], acc[nt][1], acc[nt][2], acc[nt][3],
                         a0, a1, a2, a3, b0, b1);
            }
        }
    }
}

__device__ __forceinline__ void stage_accs(float* stg, int wm, int gID, int tig,
                                           float acc[2][4]) {
#pragma unroll
    for (int nt = 0; nt < 2; ++nt)
#pragma unroll
        for (int er = 0; er < 2; ++er)
#pragma unroll
            for (int e = 0; e < 2; ++e)
                stg[(wm * 16 + gID + er * 8) * 17 + nt * 8 + tig * 2 + e] =
                    acc[nt][er * 2 + e];
}

__global__ void __launch_bounds__(256) lstm_step0_mma(
        const int* __restrict__ seq_len, const float* __restrict__ W0h, int t) {
    extern __shared__ float dynsm[];
    const int tid = threadIdx.x, lane = tid & 31, wm = tid >> 5;
    const int gID = lane >> 2, tig = lane & 3;
    const int j0 = blockIdx.x * 4;
    const int rb = t & 1, wb = rb ^ 1;
    const float* __restrict__ hbuf = g_h0[rb];

    StepPre P;
#pragma unroll
    for (int i = 0; i < 2; ++i) {
        int cc = lane + i * 32;
        int b_ = wm * 16 + (cc & 15);
        int j  = j0 + (cc >> 4);
        P.b_[i] = b_; P.j_[i] = j;
        size_t base = ((size_t)b_ * Tq + t) * Gq;
#pragma unroll
        for (int g = 0; g < 4; ++g) P.ga[i][g] = __ldg(&g_xw0[base + g * Hq + j]);
        P.cold[i] = g_c0[b_ * Hq + j];
        P.hold[i] = hbuf[b_ * Hq + j];
        P.sl[i]   = __ldg(&seq_len[b_]);
    }

    float acc[2][4] = {};
    step_mma_loop(hbuf, hbuf, W0h, W0h, 1, j0, dynsm, tid, wm, gID, tig, acc);

    __syncthreads();
    float* stg = dynsm;
    stage_accs(stg, wm, gID, tig, acc);
    __syncwarp();
#pragma unroll
    for (int i = 0; i < 2; ++i) {
        int cc = lane + i * 32;
        int row = wm * 16 + (cc & 15), jl = cc >> 4;
        float gi = stg[row * 17 + 0 + jl] + P.ga[i][0];
        float gc_= stg[row * 17 + 4 + jl] + P.ga[i][1];
        float gf = stg[row * 17 + 8 + jl] + P.ga[i][2];
        float go = stg[row * 17 + 12 + jl] + P.ga[i][3];
        bool m = t < P.sl[i];
        int s = P.b_[i] * Hq + P.j_[i];
        float cn = sigf(gf) * P.cold[i] + sigf(gi) * tanhf(gc_);
        float hn = sigf(go) * tanhf(cn);
        g_c0[s]     = m ? cn : P.cold[i];
        g_h0[wb][s] = m ? hn : P.hold[i];
        g_o0[s]     = m ? hn : 0.f;
    }
}

__global__ void __launch_bounds__(256) lstm_step1_mma(
        const int* __restrict__ seq_len,
        const float* __restrict__ W1x, const float* __restrict__ W1h,
        const float* __restrict__ b1, int t) {
    extern __shared__ float dynsm[];
    const int tid = threadIdx.x, lane = tid & 31, wm = tid >> 5;
    const int gID = lane >> 2, tig = lane & 3;
    const int j0 = blockIdx.x * 4;
    const int rb = t & 1, wb = rb ^ 1;
    const float* __restrict__ h1buf = g_h1[rb];

    StepPre P;
#pragma unroll
    for (int i = 0; i < 2; ++i) {
        int cc = lane + i * 32;
        int b_ = wm * 16 + (cc & 15);
        int j  = j0 + (cc >> 4);
        P.b_[i] = b_; P.j_[i] = j;
#pragma unroll
        for (int g = 0; g < 4; ++g) P.ga[i][g] = __ldg(&b1[g * Hq + j]);
        P.cold[i] = g_c1[b_ * Hq + j];
        P.hold[i] = h1buf[b_ * Hq + j];
        P.sl[i]   = __ldg(&seq_len[b_]);
    }

    float acc[2][4] = {};
    step_mma_loop(g_o0, h1buf, W1x, W1h, 2, j0, dynsm, tid, wm, gID, tig, acc);

    __syncthreads();
    float* stg = dynsm;
    stage_accs(stg, wm, gID, tig, acc);
    __syncwarp();
#pragma unroll
    for (int i = 0; i < 2; ++i) {
        int cc = lane + i * 32;
        int row = wm * 16 + (cc & 15), jl = cc >> 4;
        float gi = stg[row * 17 + 0 + jl] + P.ga[i][0];
        float gc_= stg[row * 17 + 4 + jl] + P.ga[i][1];
        float gf = stg[row * 17 + 8 + jl] + P.ga[i][2];
        float go = stg[row * 17 + 12 + jl] + P.ga[i][3];
        bool m = t < P.sl[i];
        int s = P.b_[i] * Hq + P.j_[i];
        float cn = sigf(gf) * P.cold[i] + sigf(gi) * tanhf(gc_);
        float hn = sigf(go) * tanhf(cn);
        g_c1[s]     = m ? cn : P.cold[i];
        g_h1[wb][s] = m ? hn : P.hold[i];
        g_out[((size_t)P.b_[i] * Tq + t) * Hq + P.j_[i]] = m ? hn : 0.f;
    }
}

// ---------------- partial softmax merge; xent ----------------
__global__ void k_xent_reduce() {
    const int row  = blockIdx.x * 8 + (threadIdx.x >> 5);
    const int lane = threadIdx.x & 31;
    float m = -1e30f, s = 0.f;
    for (int p = lane; p < NBLK; p += 32) {
        float m2 = g_pm[(size_t)row * NBLK + p];
        float s2 = g_ps[(size_t)row * NBLK + p];
        float M = fmaxf(m, m2);
        s = s * expf(m - M) + s2 * expf(m2 - M);
        m = M;
    }
#pragma unroll
    for (int o = 16; o > 0; o >>= 1) {
        float m2 = __shfl_xor_sync(0xffffffff, m, o);
        float s2 = __shfl_xor_sync(0xffffffff, s, o);
        float M = fmaxf(m, m2);
        s = s * expf(m - M) + s2 * expf(m2 - M);
        m = M;
    }
    if (lane == 0) g_xent[row] = -(g_zl[row] - m - logf(s));
}

// ---------------- final masked reduction ----------------
__global__ void k_loss(const float* __restrict__ seq_mask, float* __restrict__ out) {
    const int t = threadIdx.x;
    float sx = 0.f, sw_ = 0.f;
    for (int b = 0; b < Bq; ++b) {
        int i = b * Tq + t;
        float w = seq_mask[i];
        sx  += g_xent[i] * w;
        sw_ += w;
    }
    __shared__ float sh[64];
    sh[t] = sx / (sw_ + 1e-12f);
    __syncthreads();
    for (int o = 32; o > 0; o >>= 1) { if (t < o) sh[t] += sh[t + o]; __syncthreads(); }
    if (t == 0) out[0] = sh[0] / Tq;
}

// ---------------- launch ----------------
extern "C" void kernel_launch(void* const* d_in, const int* in_sizes, int n_in,
                              void* d_out, int out_size) {
    const int*   features = (const int*)  d_in[0];
    const int*   labels   = (const int*)  d_in[1];
    const int*   seq_len  = (const int*)  d_in[2];
    const float* seq_mask = (const float*)d_in[3];
    const float* emb      = (const float*)d_in[4];
    const float* W0x      = (const float*)d_in[5];
    const float* W0h      = (const float*)d_in[6];
    const float* b0       = (const float*)d_in[7];
    const float* W1x      = (const float*)d_in[8];
    const float* W1h      = (const float*)d_in[9];
    const float* b1       = (const float*)d_in[10];
    const float* smw      = (const float*)d_in[11];
    const float* smb      = (const float*)d_in[12];
    float* out = (float*)d_out;

    cudaFuncSetAttribute(lstm_step0_mma,
                         cudaFuncAttributeMaxDynamicSharedMemorySize, STEP_SMEM);
    cudaFuncSetAttribute(lstm_step1_mma,
                         cudaFuncAttributeMaxDynamicSharedMemorySize, STEP_SMEM);

    k_init<<<(Bq * Hq + 255) / 256, 256>>>();

    k_xw0_tf32<<<dim3(Gq / 128, BTq / 128), 256>>>(emb, features, W0x, b0);

    for (int t = 0; t < Tq; ++t) {
        lstm_step0_mma<<<128, 256, STEP_SMEM>>>(seq_len, W0h, t);
        lstm_step1_mma<<<128, 256, STEP_SMEM>>>(seq_len, W1x, W1h, b1, t);
    }

    k_logits_tf32<<<dim3(NBLK, BTq / 128), 256>>>(smw, smb, labels);
    k_xent_reduce<<<BTq / 8, 256>>>();
    k_loss<<<1, 64>>>(seq_mask, out);
}

// round 10
// speedup vs baseline: 1.2048x; 1.2048x over previous
#include <cuda_runtime.h>
#include <cuda_bf16.h>
#include <cstddef>
#include <cstdint>

#define Bq   128
#define Tq   64
#define Hq   512
#define Vq   10000
#define Gq   2048            // 4*H
#define BTq  (Bq*Tq)         // 8192
#define NBLK 79              // ceil(V/128)

// ---------------- scratch ----------------
__device__ float g_xw0[(size_t)BTq * Gq];
__device__ float g_out[(size_t)BTq * Hq];
__device__ float g_pm[(size_t)BTq * NBLK];
__device__ float g_ps[(size_t)BTq * NBLK];
__device__ float g_zl[BTq];
__device__ float g_xent[BTq];
__device__ float g_h0[2][Bq * Hq];
__device__ float g_h1[2][Bq * Hq];
__device__ float g_c0[Bq * Hq];
__device__ float g_c1[Bq * Hq];
__device__ float g_o0[2][Bq * Hq];    // double-buffered by t parity (fusion race fix)

__device__ __forceinline__ float sigf(float x) { return 1.f / (1.f + expf(-x)); }

__device__ __forceinline__ uint32_t s2u(const void* p) {
    return (uint32_t)__cvta_generic_to_shared(p);
}
__device__ __forceinline__ void cpa16(uint32_t dst, const void* src) {
    asm volatile("cp.async.cg.shared.global [%0], [%1], 16;" :: "r"(dst), "l"(src));
}
__device__ __forceinline__ void cpa16p(uint32_t dst, const void* src, bool pred) {
    int sz = pred ? 16 : 0;
    asm volatile("cp.async.cg.shared.global [%0], [%1], 16, %2;" :: "r"(dst), "l"(src), "r"(sz));
}
#define CP_COMMIT asm volatile("cp.async.commit_group;")
#define CP_WAIT1  asm volatile("cp.async.wait_group 1;")
#define CP_WAIT3  asm volatile("cp.async.wait_group 3;")

__device__ __forceinline__ void mma_tf32(float& d0, float& d1, float& d2, float& d3,
                                         unsigned a0, unsigned a1, unsigned a2, unsigned a3,
                                         unsigned b0, unsigned b1) {
    asm volatile(
        "mma.sync.aligned.m16n8k8.row.col.f32.tf32.tf32.f32 "
        "{%0,%1,%2,%3}, {%4,%5,%6,%7}, {%8,%9}, {%0,%1,%2,%3};"
        : "+f"(d0), "+f"(d1), "+f"(d2), "+f"(d3)
        : "r"(a0), "r"(a1), "r"(a2), "r"(a3), "r"(b0), "r"(b1));
}

// ---------------- init ----------------
__global__ void k_init() {
    int i = blockIdx.x * blockDim.x + threadIdx.x;
    if (i < Bq * Hq) {
        g_h0[0][i] = 0.f; g_c0[i] = 0.f;
        g_h1[0][i] = 0.f; g_c1[i] = 0.f;
    }
}

// =======================================================================
// big tf32 GEMMs: block 128x128, warp 32x64, k-chunk 16, 2-stage cp.async
// =======================================================================
#define ASTR 20
#define BSTR 136

__global__ void k_xw0_tf32(const float* __restrict__ emb, const int* __restrict__ feat,
                           const float* __restrict__ Bm, const float* __restrict__ bias) {
    const int N = Gq, K = Hq;
    __shared__ float As[2][128 * ASTR];
    __shared__ float Bs[2][16 * BSTR];
    const int tid = threadIdx.x;
    const int bx = blockIdx.x, by = blockIdx.y;
    const int warp = tid >> 5, lane = tid & 31;
    const int wm = warp & 3, wn = warp >> 2;
    const int gID = lane >> 2, tig = lane & 3;

    const int arow = tid >> 2;
    const int aq   = (tid & 3) * 4;
    const float* asrc0 = emb + (size_t)feat[by * 128 + arow] * K + aq;
    const float* asrc1 = emb + (size_t)feat[by * 128 + arow + 64] * K + aq;
    const int bk = tid >> 5, bq = tid & 31;
    const float* bsrc = Bm + (size_t)bk * N + bx * 128 + bq * 4;

    float acc[2][8][4];
#pragma unroll
    for (int mt = 0; mt < 2; ++mt)
#pragma unroll
        for (int nt = 0; nt < 8; ++nt)
#pragma unroll
            for (int e = 0; e < 4; ++e) acc[mt][nt][e] = 0.f;

    const int NC = K / 16;
    {
        cpa16(s2u(&As[0][arow * ASTR + aq]), asrc0);
        cpa16(s2u(&As[0][(arow + 64) * ASTR + aq]), asrc1);
        cpa16(s2u(&Bs[0][bk * BSTR + bq * 4]), bsrc);
        cpa16(s2u(&Bs[0][(bk + 8) * BSTR + bq * 4]), bsrc + (size_t)8 * N);
    }
    CP_COMMIT;
    for (int c = 0; c < NC; ++c) {
        const int cur = c & 1, nxt = cur ^ 1;
        if (c + 1 < NC) {
            int k0 = (c + 1) * 16;
            cpa16(s2u(&As[nxt][arow * ASTR + aq]), asrc0 + k0);
            cpa16(s2u(&As[nxt][(arow + 64) * ASTR + aq]), asrc1 + k0);
            cpa16(s2u(&Bs[nxt][bk * BSTR + bq * 4]), bsrc + (size_t)k0 * N);
            cpa16(s2u(&Bs[nxt][(bk + 8) * BSTR + bq * 4]), bsrc + (size_t)(k0 + 8) * N);
        }
        CP_COMMIT;
        CP_WAIT1;
        __syncthreads();
        const unsigned* Au = (const unsigned*)As[cur];
        const unsigned* Bu = (const unsigned*)Bs[cur];
#pragma unroll
        for (int ks = 0; ks < 2; ++ks) {
            unsigned a[2][4];
#pragma unroll
            for (int mt = 0; mt < 2; ++mt) {
                int mr = wm * 32 + mt * 16;
                a[mt][0] = Au[(mr + gID    ) * ASTR + ks * 8 + tig];
                a[mt][1] = Au[(mr + gID + 8) * ASTR + ks * 8 + tig];
                a[mt][2] = Au[(mr + gID    ) * ASTR + ks * 8 + tig + 4];
                a[mt][3] = Au[(mr + gID + 8) * ASTR + ks * 8 + tig + 4];
            }
#pragma unroll
            for (int nt = 0; nt < 8; ++nt) {
                int nc = wn * 64 + nt * 8 + gID;
                unsigned b0 = Bu[(ks * 8 + tig    ) * BSTR + nc];
                unsigned b1 = Bu[(ks * 8 + tig + 4) * BSTR + nc];
#pragma unroll
                for (int mt = 0; mt < 2; ++mt)
                    mma_tf32(acc[mt][nt][0], acc[mt][nt][1], acc[mt][nt][2], acc[mt][nt][3],
                             a[mt][0], a[mt][1], a[mt][2], a[mt][3], b0, b1);
            }
        }
        __syncthreads();
    }
#pragma unroll
    for (int mt = 0; mt < 2; ++mt) {
#pragma unroll
        for (int er = 0; er < 2; ++er) {
            int gm = by * 128 + wm * 32 + mt * 16 + gID + er * 8;
            float* crow = g_xw0 + (size_t)gm * N;
#pragma unroll
            for (int nt = 0; nt < 8; ++nt) {
                int gn = bx * 128 + wn * 64 + nt * 8 + tig * 2;
                float2 v = {acc[mt][nt][er * 2 + 0] + bias[gn],
                            acc[mt][nt][er * 2 + 1] + bias[gn + 1]};
                *(float2*)(crow + gn) = v;
            }
        }
    }
}

__global__ void k_logits_tf32(const float* __restrict__ Bm,
                              const float* __restrict__ bias,
                              const int* __restrict__ labels) {
    const int N = Vq, K = Hq;
    __shared__ float As[2][128 * ASTR];
    __shared__ float Bs[2][16 * BSTR];
    __shared__ float pm[128][9];
    __shared__ float ps[128][9];
    const int tid = threadIdx.x;
    const int bx = blockIdx.x, by = blockIdx.y;
    const int warp = tid >> 5, lane = tid & 31;
    const int wm = warp & 3, wn = warp >> 2;
    const int gID = lane >> 2, tig = lane & 3;

    const int arow = tid >> 2;
    const int aq   = (tid & 3) * 4;
    const float* asrc0 = g_out + (size_t)(by * 128 + arow) * K + aq;
    const float* asrc1 = asrc0 + (size_t)64 * K;
    const int bk = tid >> 5, bq = tid & 31;
    const int gnq = bx * 128 + bq * 4;
    const bool bpred = (gnq + 3 < N);
    const float* bsrc = Bm + (size_t)bk * N + (bpred ? gnq : 0);

    float acc[2][8][4];
#pragma unroll
    for (int mt = 0; mt < 2; ++mt)
#pragma unroll
        for (int nt = 0; nt < 8; ++nt)
#pragma unroll
            for (int e = 0; e < 4; ++e) acc[mt][nt][e] = 0.f;

    const int NC = K / 16;
    {
        cpa16(s2u(&As[0][arow * ASTR + aq]), asrc0);
        cpa16(s2u(&As[0][(arow + 64) * ASTR + aq]), asrc1);
        cpa16p(s2u(&Bs[0][bk * BSTR + bq * 4]), bsrc, bpred);
        cpa16p(s2u(&Bs[0][(bk + 8) * BSTR + bq * 4]), bsrc + (size_t)8 * N, bpred);
    }
    CP_COMMIT;
    for (int c = 0; c < NC; ++c) {
        const int cur = c & 1, nxt = cur ^ 1;
        if (c + 1 < NC) {
            int k0 = (c + 1) * 16;
            cpa16(s2u(&As[nxt][arow * ASTR + aq]), asrc0 + k0);
            cpa16(s2u(&As[nxt][(arow + 64) * ASTR + aq]), asrc1 + k0);
            cpa16p(s2u(&Bs[nxt][bk * BSTR + bq * 4]), bsrc + (size_t)k0 * N, bpred);
            cpa16p(s2u(&Bs[nxt][(bk + 8) * BSTR + bq * 4]), bsrc + (size_t)(k0 + 8) * N, bpred);
        }
        CP_COMMIT;
        CP_WAIT1;
        __syncthreads();
        const unsigned* Au = (const unsigned*)As[cur];
        const unsigned* Bu = (const unsigned*)Bs[cur];
#pragma unroll
        for (int ks = 0; ks < 2; ++ks) {
            unsigned a[2][4];
#pragma unroll
            for (int mt = 0; mt < 2; ++mt) {
                int mr = wm * 32 + mt * 16;
                a[mt][0] = Au[(mr + gID    ) * ASTR + ks * 8 + tig];
                a[mt][1] = Au[(mr + gID + 8) * ASTR + ks * 8 + tig];
                a[mt][2] = Au[(mr + gID    ) * ASTR + ks * 8 + tig + 4];
                a[mt][3] = Au[(mr + gID + 8) * ASTR + ks * 8 + tig + 4];
            }
#pragma unroll
            for (int nt = 0; nt < 8; ++nt) {
                int nc = wn * 64 + nt * 8 + gID;
                unsigned b0 = Bu[(ks * 8 + tig    ) * BSTR + nc];
                unsigned b1 = Bu[(ks * 8 + tig + 4) * BSTR + nc];
#pragma unroll
                for (int mt = 0; mt < 2; ++mt)
                    mma_tf32(acc[mt][nt][0], acc[mt][nt][1], acc[mt][nt][2], acc[mt][nt][3],
                             a[mt][0], a[mt][1], a[mt][2], a[mt][3], b0, b1);
            }
        }
        __syncthreads();
    }

#pragma unroll
    for (int mt = 0; mt < 2; ++mt) {
#pragma unroll
        for (int er = 0; er < 2; ++er) {
            int lr = wm * 32 + mt * 16 + gID + er * 8;
            int gm = by * 128 + lr;
            int lab = labels[gm];
            float lm = -1e30f, lsum = 0.f;
            float v[16];
#pragma unroll
            for (int nt = 0; nt < 8; ++nt) {
#pragma unroll
                for (int e = 0; e < 2; ++e) {
                    int gn = bx * 128 + wn * 64 + nt * 8 + tig * 2 + e;
                    float cc = acc[mt][nt][er * 2 + e];
                    if (gn < N) {
                        float z = cc + bias[gn];
                        v[nt * 2 + e] = z;
                        if (gn == lab) g_zl[gm] = z;
                        lm = fmaxf(lm, z);
                    } else v[nt * 2 + e] = -1e30f;
                }
            }
#pragma unroll
            for (int q = 0; q < 16; ++q) lsum += expf(v[q] - lm);
            if (lm <= -1e30f) lsum = 0.f;
            pm[lr][wn * 4 + tig] = lm;
            ps[lr][wn * 4 + tig] = lsum;
        }
    }
    __syncthreads();
    if (tid < 128) {
        float m = -1e30f, s = 0.f;
#pragma unroll
        for (int x = 0; x < 8; ++x) {
            float m2 = pm[tid][x], s2 = ps[tid][x];
            float M = fmaxf(m, m2);
            s = s * expf(m - M) + s2 * expf(m2 - M);
            m = M;
        }
        int gm = by * 128 + tid;
        g_pm[(size_t)gm * NBLK + bx] = m;
        g_ps[(size_t)gm * NBLK + bx] = s;
    }
}

// =======================================================================
// tf32 tensor-core LSTM layers as __device__ bodies (R8 proven structure:
// k-chunk 16, 4-stage cp.async, two syncs/iter).  SMEM 4x(A[128][20]+B[16][24])
// = 46 KB static.  Fused kernel runs layer1(t) on blocks 0-127 and
// layer0(t+1) on blocks 128-255 concurrently (independent).
// =======================================================================
#define SA  20
#define SB  24
#define NSTG 4

__device__ __forceinline__ void step_mma_loop(
        const float* __restrict__ A0, const float* __restrict__ A1,
        const float* __restrict__ W0, const float* __restrict__ W1,
        int nphase, int j0, float* AsmBase, float* BsmBase,
        int tid, int wm, int gID, int tig, float acc[2][4]) {
    const int ar = tid >> 1, aq = (tid & 1) * 8;
    const int bk = tid >> 2, bg = tid & 3;          // tid<64 fills B
    const int NC = nphase * 32;

    auto issue = [&](int cc) {
        const float* Ap = (cc < 32) ? A0 : A1;
        const float* Wp = (cc < 32) ? W0 : W1;
        int k0 = (cc & 31) * 16;
        float* Ab = AsmBase + (cc & (NSTG - 1)) * (128 * SA);
        float* Bb = BsmBase + (cc & (NSTG - 1)) * (16 * SB);
        cpa16(s2u(&Ab[ar * SA + aq]),     Ap + (size_t)ar * Hq + k0 + aq);
        cpa16(s2u(&Ab[ar * SA + aq + 4]), Ap + (size_t)ar * Hq + k0 + aq + 4);
        if (tid < 64)
            cpa16(s2u(&Bb[bk * SB + bg * 4]),
                  Wp + (size_t)(k0 + bk) * Gq + bg * Hq + j0);
    };

#pragma unroll
    for (int s = 0; s < NSTG - 1; ++s) { issue(s); CP_COMMIT; }

    for (int c = 0; c < NC; ++c) {
        if (c + NSTG - 1 < NC) issue(c + NSTG - 1);
        CP_COMMIT;                 // unconditional: group index == chunk index
        CP_WAIT3;                  // chunk c retired
        __syncthreads();
        const unsigned* Au = (const unsigned*)(AsmBase + (c & (NSTG - 1)) * (128 * SA));
        const unsigned* Bu = (const unsigned*)(BsmBase + (c & (NSTG - 1)) * (16 * SB));
#pragma unroll
        for (int ks = 0; ks < 2; ++ks) {
            unsigned a0 = Au[(wm * 16 + gID    ) * SA + ks * 8 + tig];
            unsigned a1 = Au[(wm * 16 + gID + 8) * SA + ks * 8 + tig];
            unsigned a2 = Au[(wm * 16 + gID    ) * SA + ks * 8 + tig + 4];
            unsigned a3 = Au[(wm * 16 + gID + 8) * SA + ks * 8 + tig + 4];
#pragma unroll
            for (int nt = 0; nt < 2; ++nt) {
                int n = nt * 8 + gID;
                unsigned b0 = Bu[(ks * 8 + tig    ) * SB + n];
                unsigned b1 = Bu[(ks * 8 + tig + 4) * SB + n];
                mma_tf32(acc[nt][0], acc[nt][1], acc[nt][2], acc[nt][3],
                         a0, a1, a2, a3, b0, b1);
            }
        }
        __syncthreads();
    }
}

__device__ __forceinline__ void stage_accs(float* stg, int wm, int gID, int tig,
                                           float acc[2][4]) {
#pragma unroll
    for (int nt = 0; nt < 2; ++nt)
#pragma unroll
        for (int er = 0; er < 2; ++er)
#pragma unroll
            for (int e = 0; e < 2; ++e)
                stg[(wm * 16 + gID + er * 8) * 17 + nt * 8 + tig * 2 + e] =
                    acc[nt][er * 2 + e];
}

// ---- layer 0 body: gates = h0 @ W0h + xw0[t]; writes h0[wb], o0[t&1], c0 ----
__device__ void layer0_body(int t, int jblk, const int* __restrict__ seq_len,
                            const float* __restrict__ W0h,
                            float* Asm, float* Bsm) {
    const int tid = threadIdx.x, lane = tid & 31, wm = tid >> 5;
    const int gID = lane >> 2, tig = lane & 3;
    const int j0 = jblk * 4;
    const int rb = t & 1, wb = rb ^ 1;
    const float* __restrict__ hbuf = g_h0[rb];

    float ga[2][4], cold[2], hold[2];
    int sl[2], bb_[2], jj_[2];
#pragma unroll
    for (int i = 0; i < 2; ++i) {
        int cc = lane + i * 32;
        int b_ = wm * 16 + (cc & 15);
        int j  = j0 + (cc >> 4);
        bb_[i] = b_; jj_[i] = j;
        size_t base = ((size_t)b_ * Tq + t) * Gq;
#pragma unroll
        for (int g = 0; g < 4; ++g) ga[i][g] = __ldg(&g_xw0[base + g * Hq + j]);
        cold[i] = g_c0[b_ * Hq + j];
        hold[i] = hbuf[b_ * Hq + j];
        sl[i]   = __ldg(&seq_len[b_]);
    }

    float acc[2][4] = {};
    step_mma_loop(hbuf, hbuf, W0h, W0h, 1, j0, Asm, Bsm, tid, wm, gID, tig, acc);

    __syncthreads();
    stage_accs(Asm, wm, gID, tig, acc);
    __syncwarp();
#pragma unroll
    for (int i = 0; i < 2; ++i) {
        int cc = lane + i * 32;
        int row = wm * 16 + (cc & 15), jl = cc >> 4;
        float gi = Asm[row * 17 + 0 + jl] + ga[i][0];
        float gc_= Asm[row * 17 + 4 + jl] + ga[i][1];
        float gf = Asm[row * 17 + 8 + jl] + ga[i][2];
        float go = Asm[row * 17 + 12 + jl] + ga[i][3];
        bool m = t < sl[i];
        int s = bb_[i] * Hq + jj_[i];
        float cn = sigf(gf) * cold[i] + sigf(gi) * tanhf(gc_);
        float hn = sigf(go) * tanhf(cn);
        g_c0[s]        = m ? cn : cold[i];
        g_h0[wb][s]    = m ? hn : hold[i];
        g_o0[t & 1][s] = m ? hn : 0.f;
    }
}

// ---- layer 1 body: gates = o0[t&1] @ W1x + h1 @ W1h + b1 ----
__device__ void layer1_body(int t, int jblk, const int* __restrict__ seq_len,
                            const float* __restrict__ W1x, const float* __restrict__ W1h,
                            const float* __restrict__ b1,
                            float* Asm, float* Bsm) {
    const int tid = threadIdx.x, lane = tid & 31, wm = tid >> 5;
    const int gID = lane >> 2, tig = lane & 3;
    const int j0 = jblk * 4;
    const int rb = t & 1, wb = rb ^ 1;
    const float* __restrict__ h1buf = g_h1[rb];

    float ga[2][4], cold[2], hold[2];
    int sl[2], bb_[2], jj_[2];
#pragma unroll
    for (int i = 0; i < 2; ++i) {
        int cc = lane + i * 32;
        int b_ = wm * 16 + (cc & 15);
        int j  = j0 + (cc >> 4);
        bb_[i] = b_; jj_[i] = j;
#pragma unroll
        for (int g = 0; g < 4; ++g) ga[i][g] = __ldg(&b1[g * Hq + j]);
        cold[i] = g_c1[b_ * Hq + j];
        hold[i] = h1buf[b_ * Hq + j];
        sl[i]   = __ldg(&seq_len[b_]);
    }

    float acc[2][4] = {};
    step_mma_loop(g_o0[t & 1], h1buf, W1x, W1h, 2, j0, Asm, Bsm, tid, wm, gID, tig, acc);

    __syncthreads();
    stage_accs(Asm, wm, gID, tig, acc);
    __syncwarp();
#pragma unroll
    for (int i = 0; i < 2; ++i) {
        int cc = lane + i * 32;
        int row = wm * 16 + (cc & 15), jl = cc >> 4;
        float gi = Asm[row * 17 + 0 + jl] + ga[i][0];
        float gc_= Asm[row * 17 + 4 + jl] + ga[i][1];
        float gf = Asm[row * 17 + 8 + jl] + ga[i][2];
        float go = Asm[row * 17 + 12 + jl] + ga[i][3];
        bool m = t < sl[i];
        int s = bb_[i] * Hq + jj_[i];
        float cn = sigf(gf) * cold[i] + sigf(gi) * tanhf(gc_);
        float hn = sigf(go) * tanhf(cn);
        g_c1[s]     = m ? cn : cold[i];
        g_h1[wb][s] = m ? hn : hold[i];
        g_out[((size_t)bb_[i] * Tq + t) * Hq + jj_[i]] = m ? hn : 0.f;
    }
}

__global__ void __launch_bounds__(256) lstm_l0_only(const int* __restrict__ seq_len,
                                                    const float* __restrict__ W0h, int t) {
    __shared__ float Asm[NSTG][128 * SA];
    __shared__ float Bsm[NSTG][16 * SB];
    layer0_body(t, blockIdx.x, seq_len, W0h, &Asm[0][0], &Bsm[0][0]);
}

__global__ void __launch_bounds__(256) lstm_l1_only(const int* __restrict__ seq_len,
                                                    const float* __restrict__ W1x,
                                                    const float* __restrict__ W1h,
                                                    const float* __restrict__ b1, int t) {
    __shared__ float Asm[NSTG][128 * SA];
    __shared__ float Bsm[NSTG][16 * SB];
    layer1_body(t, blockIdx.x, seq_len, W1x, W1h, b1, &Asm[0][0], &Bsm[0][0]);
}

// fused: blocks 0-127 -> layer1(t);  blocks 128-255 -> layer0(t+1)
__global__ void __launch_bounds__(256) lstm_fused(const int* __restrict__ seq_len,
                                                  const float* __restrict__ W0h,
                                                  const float* __restrict__ W1x,
                                                  const float* __restrict__ W1h,
                                                  const float* __restrict__ b1, int t) {
    __shared__ float Asm[NSTG][128 * SA];
    __shared__ float Bsm[NSTG][16 * SB];
    if (blockIdx.x < 128)
        layer1_body(t, blockIdx.x, seq_len, W1x, W1h, b1, &Asm[0][0], &Bsm[0][0]);
    else
        layer0_body(t + 1, blockIdx.x - 128, seq_len, W0h, &Asm[0][0], &Bsm[0][0]);
}

// ---------------- partial softmax merge; xent ----------------
__global__ void k_xent_reduce() {
    const int row  = blockIdx.x * 8 + (threadIdx.x >> 5);
    const int lane = threadIdx.x & 31;
    float m = -1e30f, s = 0.f;
    for (int p = lane; p < NBLK; p += 32) {
        float m2 = g_pm[(size_t)row * NBLK + p];
        float s2 = g_ps[(size_t)row * NBLK + p];
        float M = fmaxf(m, m2);
        s = s * expf(m - M) + s2 * expf(m2 - M);
        m = M;
    }
#pragma unroll
    for (int o = 16; o > 0; o >>= 1) {
        float m2 = __shfl_xor_sync(0xffffffff, m, o);
        float s2 = __shfl_xor_sync(0xffffffff, s, o);
        float M = fmaxf(m, m2);
        s = s * expf(m - M) + s2 * expf(m2 - M);
        m = M;
    }
    if (lane == 0) g_xent[row] = -(g_zl[row] - m - logf(s));
}

// ---------------- final masked reduction ----------------
__global__ void k_loss(const float* __restrict__ seq_mask, float* __restrict__ out) {
    const int t = threadIdx.x;
    float sx = 0.f, sw_ = 0.f;
    for (int b = 0; b < Bq; ++b) {
        int i = b * Tq + t;
        float w = seq_mask[i];
        sx  += g_xent[i] * w;
        sw_ += w;
    }
    __shared__ float sh[64];
    sh[t] = sx / (sw_ + 1e-12f);
    __syncthreads();
    for (int o = 32; o > 0; o >>= 1) { if (t < o) sh[t] += sh[t + o]; __syncthreads(); }
    if (t == 0) out[0] = sh[0] / Tq;
}

// ---------------- launch ----------------
extern "C" void kernel_launch(void* const* d_in, const int* in_sizes, int n_in,
                              void* d_out, int out_size) {
    const int*   features = (const int*)  d_in[0];
    const int*   labels   = (const int*)  d_in[1];
    const int*   seq_len  = (const int*)  d_in[2];
    const float* seq_mask = (const float*)d_in[3];
    const float* emb      = (const float*)d_in[4];
    const float* W0x      = (const float*)d_in[5];
    const float* W0h      = (const float*)d_in[6];
    const float* b0       = (const float*)d_in[7];
    const float* W1x      = (const float*)d_in[8];
    const float* W1h      = (const float*)d_in[9];
    const float* b1       = (const float*)d_in[10];
    const float* smw      = (const float*)d_in[11];
    const float* smb      = (const float*)d_in[12];
    float* out = (float*)d_out;

    k_init<<<(Bq * Hq + 255) / 256, 256>>>();

    k_xw0_tf32<<<dim3(Gq / 128, BTq / 128), 256>>>(emb, features, W0x, b0);

    // software-pipelined recurrence: L0(0); { L1(t) || L0(t+1) } x63; L1(63)
    lstm_l0_only<<<128, 256>>>(seq_len, W0h, 0);
    for (int t = 0; t < Tq - 1; ++t)
        lstm_fused<<<256, 256>>>(seq_len, W0h, W1x, W1h, b1, t);
    lstm_l1_only<<<128, 256>>>(seq_len, W1x, W1h, b1, Tq - 1);

    k_logits_tf32<<<dim3(NBLK, BTq / 128), 256>>>(smw, smb, labels);
    k_xent_reduce<<<BTq / 8, 256>>>();
    k_loss<<<1, 64>>>(seq_mask, out);
}